// round 8
// baseline (speedup 1.0000x reference)
#include <cuda_runtime.h>
#include <cuda_bf16.h>

// CRF NLL: out = -(sum_b (score_b - partition_b)),  B=512, S=1024, T=32.
//
// Partition via BIDIRECTIONAL linear-domain recurrence with power-of-2
// rescaling (halves the serial chain: 512 steps/warp instead of 1024):
//   forward : alpha_s = D(e_s) M^T alpha_{s-1},   s = 1..512
//   backward: g_s     = M (e_{s+1} ∘ g_{s+1}),    s = 1022..512  (g_1023 = exp(end))
//   Z = g_512 · alpha_512, each side tracked as v * 2^off with per-step
//   2^-k scaling, k = exponent of (one-step-stale) component 0.
// tags buffer is int32 on device (JAX x64-disabled downcast of jnp.int64).

#define BB 512
#define SS 1024
#define TT 32
#define PD 8
#define LN2F 0.6931471805599453f

__device__ float    g_partial[BB];
__device__ unsigned g_ctr = 0;

__device__ __forceinline__ float warp_sum(float v) {
#pragma unroll
    for (int o = 16; o; o >>= 1) v += __shfl_xor_sync(0xFFFFFFFFu, v, o);
    return v;
}

__device__ __forceinline__ float matvec32(const float* __restrict__ buf,
                                          const float* __restrict__ Mreg) {
    const float4* pb = (const float4*)buf;
    float acc[8];
#pragma unroll
    for (int g = 0; g < 8; g++) {
        float4 v = pb[g];
        acc[g] = fmaf(v.x, Mreg[4 * g + 0],
                 fmaf(v.y, Mreg[4 * g + 1],
                 fmaf(v.z, Mreg[4 * g + 2], v.w * Mreg[4 * g + 3])));
    }
    return ((acc[0] + acc[1]) + (acc[2] + acc[3]))
         + ((acc[4] + acc[5]) + (acc[6] + acc[7]));
}

__global__ void __launch_bounds__(256, 1) crf_main(
    const float* __restrict__ em, const int* __restrict__ tags,
    const float* __restrict__ mask, const float* __restrict__ trans,
    const float* __restrict__ startt, const float* __restrict__ endt,
    float* __restrict__ out)
{
    __shared__ __align__(16) float sp[8][2][TT];   // per-warp double buffer
    __shared__ float tb[4][TT][33];                // transpose scratch (pad 33)
    __shared__ float comb_g[4][TT];
    __shared__ int   comb_off[4];
    __shared__ float comb_sc[8], comb_ms[8];

    const int w    = threadIdx.x >> 5;
    const int lane = threadIdx.x & 31;
    const int pair = w >> 1;           // batch slot within CTA (0..3)
    const int dir  = w & 1;            // 0 = forward, 1 = backward
    const int b    = blockIdx.x * 4 + pair;
    const size_t embase = (size_t)b * SS * TT;

    // M = exp(trans). Forward needs column lane (coalesced); backward needs
    // row lane (via padded shared transpose, conflict-free).
    float Mreg[TT];
    if (dir == 0) {
#pragma unroll
        for (int i = 0; i < TT; i++) Mreg[i] = __expf(trans[i * TT + lane]);
    } else {
#pragma unroll
        for (int i = 0; i < TT; i++) tb[pair][i][lane] = __expf(trans[i * TT + lane]);
        __syncwarp();
#pragma unroll
        for (int i = 0; i < TT; i++) Mreg[i] = tb[pair][lane][i];
    }

    // Emission/mask prefetch pipeline. Step n maps to sequence index:
    //   fwd: si = 1 + n (n = 0..511, all real)
    //   bwd: si = 1023 - n (n = 0..510 real; n = 511 is a masked dummy)
    float em_pf[PD], m_pf[PD];
#pragma unroll
    for (int u = 0; u < PD; u++) {
        int si = dir ? (1023 - u) : (1 + u);
        em_pf[u] = em[embase + (size_t)si * TT + lane];
        m_pf[u]  = mask[b * SS + si];
    }
    float ex = __expf(em_pf[0]);
    float av = 1.0f;
    int off = 0;
    int rb = 0;

    float state;
    if (dir == 0) {
        state = __expf(startt[lane] + em[embase + lane]);   // alpha0 (linear)
        sp[w][0][lane] = state;
        __syncwarp();
    } else {
        state = __expf(endt[lane]);                          // g_1023
    }

    if (dir == 0) {
#pragma unroll 1
        for (int n0 = 0; n0 < 512; n0 += PD) {
#pragma unroll
            for (int u = 0; u < PD; u++) {
                unsigned ebb  = (__float_as_uint(av) >> 23) & 0xFFu;
                int      k    = (int)ebb - 127;
                float scalef  = __uint_as_float((254u - ebb) << 23);  // 2^-k
                float emsc    = ex * scalef;
                float m       = m_pf[u];

                int  np = n0 + u + PD;                 // prefetch step n+PD
                bool ok = np < 512;
                int  si = 1 + np;
                em_pf[u] = ok ? em[embase + (size_t)si * TT + lane] : 0.f;
                m_pf[u]  = ok ? mask[b * SS + si] : 0.f;

                float A   = matvec32(sp[w][rb], Mreg); // Σ_i p_i M[i][lane]
                float avn = __shfl_sync(0xFFFFFFFFu, A, 0);
                float pn  = A * emsc;
                bool upd  = (m != 0.f);
                state = upd ? pn : state;
                off  += upd ? k : 0;
                sp[w][rb ^ 1][lane] = state;
                __syncwarp();
                rb ^= 1; av = avn;
                ex = __expf(em_pf[(u + 1) & (PD - 1)]);
            }
        }
    } else {
#pragma unroll 1
        for (int n0 = 0; n0 < 512; n0 += PD) {
#pragma unroll
            for (int u = 0; u < PD; u++) {
                unsigned ebb  = (__float_as_uint(av) >> 23) & 0xFFu;
                int      k    = (int)ebb - 127;
                float scalef  = __uint_as_float((254u - ebb) << 23);
                float m       = m_pf[u];

                int  np = n0 + u + PD;
                bool ok = np < 511;
                int  si = 1023 - np;
                em_pf[u] = ok ? em[embase + (size_t)si * TT + lane] : 0.f;
                m_pf[u]  = ok ? mask[b * SS + si] : 0.f;

                float h = state * (ex * scalef);       // e ∘ g (rescaled)
                sp[w][rb][lane] = h;
                __syncwarp();
                float Gn  = matvec32(sp[w][rb], Mreg); // Σ_j M[lane][j] h_j
                float avn = __shfl_sync(0xFFFFFFFFu, Gn, 0);
                bool upd  = (m != 0.f);
                state = upd ? Gn : state;
                off  += upd ? k : 0;
                rb ^= 1; av = avn;
                ex = __expf(em_pf[(u + 1) & (PD - 1)]);
            }
        }
    }

    if (dir) {
        comb_g[pair][lane] = state;
        if (lane == 0) comb_off[pair] = off;
    }

    // ---- gold-path score, split between the two warps of the pair ----
    float sc = 0.f, ms = 0.f;
    const int* tg = tags + (size_t)b * SS;
#pragma unroll 4
    for (int it = 0; it < 16; it++) {
        int s  = it * 64 + dir * 32 + lane;
        int tc = tg[s];
        float mm = mask[b * SS + s];
        ms += mm;
        if (s == 0) {
            sc += startt[tc] + em[embase + tc];
        } else {
            int tp = tg[s - 1];
            sc += (em[embase + (size_t)s * TT + tc] + trans[tp * TT + tc]) * mm;
        }
    }
    sc = warp_sum(sc); ms = warp_sum(ms);
    if (lane == 0) { comb_sc[w] = sc; comb_ms[w] = ms; }
    __syncthreads();

    if (dir == 0) {
        float dot = state * comb_g[pair][lane];        // Z = g_512 · alpha_512
        dot = warp_sum(dot);
        if (lane == 0) {
            float partition = logf(dot) + (float)(off + comb_off[pair]) * LN2F;
            float sct = comb_sc[w] + comb_sc[w + 1];
            int last  = (int)(comb_ms[w] + comb_ms[w + 1]) - 1;
            g_partial[b] = (sct + endt[tg[last]]) - partition;
            __threadfence();
        }
    }
    __syncthreads();

    // ---- last-CTA-done final reduction (replaces the 4us reduce kernel) ----
    if (w == 0) {
        unsigned done = 0;
        if (lane == 0) done = atomicAdd(&g_ctr, 1);
        done = __shfl_sync(0xFFFFFFFFu, done, 0);
        if (done == gridDim.x - 1) {
            __threadfence();
            float v = 0.f;
#pragma unroll
            for (int i = 0; i < BB / 32; i++) v += g_partial[lane + i * 32];
            v = warp_sum(v);
            if (lane == 0) { out[0] = -v; g_ctr = 0; }   // reset for graph replay
        }
    }
}

extern "C" void kernel_launch(void* const* d_in, const int* in_sizes, int n_in,
                              void* d_out, int out_size) {
    const float* em    = (const float*)d_in[0];
    const int*   tags  = (const int*)d_in[1];
    const float* mask  = (const float*)d_in[2];
    const float* trans = (const float*)d_in[3];
    const float* st    = (const float*)d_in[4];
    const float* en    = (const float*)d_in[5];
    (void)in_sizes; (void)n_in; (void)out_size;

    crf_main<<<BB / 4, 256>>>(em, tags, mask, trans, st, en, (float*)d_out);
}